// round 7
// baseline (speedup 1.0000x reference)
#include <cuda_runtime.h>
#include <cstdint>

// Emformer layer, sm_103a. Round 6: pre-converted tf32 operands (zero cvt in
// GEMM mainloops), packed input buffer (branchless gathers), BLOCK_Q=128 flash
// with warp-local softmax and diagonal tile skipping.
// T=1024 B=16 D=512 H=8 R=32 S=16 M=16  TQ=KL=1072, d_head=64, B*H=128.

#define TT    1024
#define BB    16
#define DDIM  512
#define HH    8
#define RR    32
#define SSUM  16
#define MMEM  16
#define TQL   1072
#define KLL   1072
#define DH    64
#define NH    128
#define NEG_INF (-100000000.0f)
#define QSCALE  (0.125f)

// Scratch (device globals; zero-initialized at load, never freed)
#define GIN_ROWS 1168   // 1088 used (mems16|rc32|utt1024|summ16) + pad rows
__device__ unsigned g_in [(size_t)GIN_ROWS * BB * DDIM];
__device__ unsigned g_wq [512 * 512];
__device__ unsigned g_wkv[1024 * 512];
__device__ unsigned g_wo [512 * 512];
__device__ unsigned g_q   [(size_t)NH * TQL * DH + 4096];
__device__ unsigned g_k   [(size_t)NH * KLL * DH + 4096];
__device__ unsigned g_vT  [(size_t)NH * DH * KLL + 4096];   // [n][d][kseq]
__device__ unsigned g_attn[(size_t)NH * TQL * DH + 4096];

__device__ __forceinline__ int read_len(const void* lptr, int b) {
    const int* p32 = (const int*)lptr;
    const bool is64 = (p32[1] == 0) & (p32[3] == 0) & (p32[5] == 0);
    return is64 ? (int)(((const long long*)lptr)[b]) : p32[b];
}

__device__ __forceinline__ unsigned f2t(float x) {
    unsigned r;
    asm("cvt.rna.tf32.f32 %0, %1;" : "=r"(r) : "f"(x));
    return r;
}
__device__ __forceinline__ void mma_t(float c[4], uint4 a, unsigned b0, unsigned b1) {
    asm("mma.sync.aligned.m16n8k8.row.col.f32.tf32.tf32.f32 "
        "{%0,%1,%2,%3},{%4,%5,%6,%7},{%8,%9},{%0,%1,%2,%3};"
        : "+f"(c[0]), "+f"(c[1]), "+f"(c[2]), "+f"(c[3])
        : "r"(a.x), "r"(a.y), "r"(a.z), "r"(a.w), "r"(b0), "r"(b1));
}

// fast exp on the FMA pipe (x <= 0)
__device__ __forceinline__ float fexp(float x) {
    float t = x * 1.44269504089f;
    t = fmaxf(t, -125.0f);
    int ii = __float2int_rn(t);
    float f = t - (float)ii;
    float p = fmaf(f, 0.00961812910f, 0.05550410866f);
    p = fmaf(f, p, 0.24022650696f);
    p = fmaf(f, p, 0.69314718056f);
    p = fmaf(f, p, 1.0f);
    return __int_as_float((ii + 127) << 23) * p;
}

// Fragment-order smem: unit (16 rows x 8 k) = 128 words, stride 132 words.
#define UPW 132
#define UP4 33

__device__ __forceinline__ void sts_afrag(unsigned* S, int k8n, int r, int c0, uint4 v) {
    const int unit = (r >> 4) * k8n + (c0 >> 3);
    const int base = unit * UPW + (r & 7) * 16 + ((r & 15) >> 3) + 2 * ((c0 & 7) >> 2);
    S[base] = v.x; S[base + 4] = v.y; S[base + 8] = v.z; S[base + 12] = v.w;
}
__device__ __forceinline__ void sts_bfrag(unsigned* S, int k8n, int r, int c0, uint4 v) {
    const int unit = (r >> 4) * k8n + (c0 >> 3);
    const int base = unit * UPW + (r & 7) * 16 + 2 * ((r & 15) >> 3) + ((c0 & 7) >> 2);
    S[base] = v.x; S[base + 4] = v.y; S[base + 8] = v.z; S[base + 12] = v.w;
}

// ---------------------------------------------------------------------------
// Prep: elementwise fp32 -> tf32-bits copy
// ---------------------------------------------------------------------------
__global__ void __launch_bounds__(256) cvt_kernel(
    const float4* __restrict__ src, uint4* __restrict__ dst, int n4)
{
    const int i = blockIdx.x * 256 + threadIdx.x;
    if (i < n4) {
        float4 v = src[i];
        dst[i] = make_uint4(f2t(v.x), f2t(v.y), f2t(v.z), f2t(v.w));
    }
}

// ---------------------------------------------------------------------------
// Projection core: block tile 128x64, K-chunk 32, 8 warps (4m x 2n).
// ---------------------------------------------------------------------------
struct ProjSmem { unsigned Af[32 * UPW]; unsigned Bf[16 * UPW]; };

__device__ __forceinline__ void proj_mma(const ProjSmem& s, int lid, int wid,
                                         float acc[2][4][4]) {
    const uint4* A4 = (const uint4*)s.Af;
    const uint4* B4 = (const uint4*)s.Bf;
    const int m16 = (wid & 3) * 2, n16 = (wid >> 2) * 2;
#pragma unroll
    for (int k8 = 0; k8 < 4; k8++) {
        uint4 a0 = A4[(m16 * 4 + k8) * UP4 + lid];
        uint4 a1 = A4[((m16 + 1) * 4 + k8) * UP4 + lid];
        uint4 b0 = B4[(n16 * 4 + k8) * UP4 + lid];
        uint4 b1 = B4[((n16 + 1) * 4 + k8) * UP4 + lid];
        mma_t(acc[0][0], a0, b0.x, b0.y); mma_t(acc[0][1], a0, b0.z, b0.w);
        mma_t(acc[0][2], a0, b1.x, b1.y); mma_t(acc[0][3], a0, b1.z, b1.w);
        mma_t(acc[1][0], a1, b0.x, b0.y); mma_t(acc[1][1], a1, b0.z, b0.w);
        mma_t(acc[1][2], a1, b1.x, b1.y); mma_t(acc[1][3], a1, b1.z, b1.w);
    }
}

#define PROJ_PROLOG \
    const int tid = threadIdx.x; \
    const int lid = tid & 31, wid = tid >> 5; \
    const int g = lid >> 2, tg = lid & 3; \
    const int warpM = (wid & 3) * 32, warpN = (wid >> 2) * 32; \
    const int lr = tid >> 3; \
    const int lc = (tid & 7) * 4; \
    float acc[2][4][4]; \
    _Pragma("unroll") for (int mt = 0; mt < 2; mt++) \
    _Pragma("unroll") for (int nt = 0; nt < 4; nt++) \
    _Pragma("unroll") for (int i = 0; i < 4; i++) acc[mt][nt][i] = 0.f;

// ---------------------------------------------------------------------------
__global__ void __launch_bounds__(256) proj_q_kernel(const float* __restrict__ bias)
{
    __shared__ ProjSmem s;
    const int t0 = blockIdx.x * 128;
    const int h = blockIdx.y, b = blockIdx.z;
    PROJ_PROLOG;

    const unsigned* ap[4];
#pragma unroll
    for (int i = 0; i < 4; i++)
        ap[i] = g_in + ((size_t)(16 + t0 + i * 32 + lr) * BB + b) * DDIM;   // q row offset 16
    const unsigned* bp0 = g_wq + (size_t)(h * 64 + lr) * DDIM;
    const unsigned* bp1 = g_wq + (size_t)(h * 64 + 32 + lr) * DDIM;

    uint4 pa[4], pb[2];
#pragma unroll
    for (int i = 0; i < 4; i++) pa[i] = *(const uint4*)(ap[i] + lc);
    pb[0] = *(const uint4*)(bp0 + lc); pb[1] = *(const uint4*)(bp1 + lc);

    for (int k0 = 0; k0 < DDIM; k0 += 32) {
        __syncthreads();
#pragma unroll
        for (int i = 0; i < 4; i++) sts_afrag(s.Af, 4, i * 32 + lr, lc, pa[i]);
        sts_bfrag(s.Bf, 4, lr, lc, pb[0]);
        sts_bfrag(s.Bf, 4, 32 + lr, lc, pb[1]);
        __syncthreads();
        if (k0 + 32 < DDIM) {
            const int kn = k0 + 32 + lc;
#pragma unroll
            for (int i = 0; i < 4; i++) pa[i] = *(const uint4*)(ap[i] + kn);
            pb[0] = *(const uint4*)(bp0 + kn); pb[1] = *(const uint4*)(bp1 + kn);
        }
        proj_mma(s, lid, wid, acc);
    }

    const size_t nb = ((size_t)(b * HH + h)) * TQL;
#pragma unroll
    for (int mt = 0; mt < 2; mt++)
#pragma unroll
    for (int nt = 0; nt < 4; nt++) {
        const int c0 = warpN + nt * 8 + 2 * tg;
        const float bx = bias[h * 64 + c0], by = bias[h * 64 + c0 + 1];
#pragma unroll
        for (int rh = 0; rh < 2; rh++) {
            const int t = t0 + warpM + mt * 16 + rh * 8 + g;
            if (t < TQL) {
                uint2 v;
                v.x = f2t((acc[mt][nt][rh * 2 + 0] + bx) * QSCALE);
                v.y = f2t((acc[mt][nt][rh * 2 + 1] + by) * QSCALE);
                *(uint2*)(g_q + (nb + t) * DH + c0) = v;
            }
        }
    }
}

// ---------------------------------------------------------------------------
__global__ void __launch_bounds__(256) proj_kv_kernel(const float* __restrict__ bias)
{
    __shared__ ProjSmem s;
    const int t0 = blockIdx.x * 128;
    const int cb = blockIdx.y, b = blockIdx.z;
    PROJ_PROLOG;

    const unsigned* ap[4];
#pragma unroll
    for (int i = 0; i < 4; i++)
        ap[i] = g_in + ((size_t)(t0 + i * 32 + lr) * BB + b) * DDIM;        // kv rows 0..
    const unsigned* bp0 = g_wkv + (size_t)(cb * 64 + lr) * DDIM;
    const unsigned* bp1 = g_wkv + (size_t)(cb * 64 + 32 + lr) * DDIM;

    uint4 pa[4], pb[2];
#pragma unroll
    for (int i = 0; i < 4; i++) pa[i] = *(const uint4*)(ap[i] + lc);
    pb[0] = *(const uint4*)(bp0 + lc); pb[1] = *(const uint4*)(bp1 + lc);

    for (int k0 = 0; k0 < DDIM; k0 += 32) {
        __syncthreads();
#pragma unroll
        for (int i = 0; i < 4; i++) sts_afrag(s.Af, 4, i * 32 + lr, lc, pa[i]);
        sts_bfrag(s.Bf, 4, lr, lc, pb[0]);
        sts_bfrag(s.Bf, 4, 32 + lr, lc, pb[1]);
        __syncthreads();
        if (k0 + 32 < DDIM) {
            const int kn = k0 + 32 + lc;
#pragma unroll
            for (int i = 0; i < 4; i++) pa[i] = *(const uint4*)(ap[i] + kn);
            pb[0] = *(const uint4*)(bp0 + kn); pb[1] = *(const uint4*)(bp1 + kn);
        }
        proj_mma(s, lid, wid, acc);
    }

    const int h = cb & 7;
    const int n = b * HH + h;
#pragma unroll
    for (int mt = 0; mt < 2; mt++)
#pragma unroll
    for (int nt = 0; nt < 4; nt++) {
        const int c0 = warpN + nt * 8 + 2 * tg;
        const float bx = bias[cb * 64 + c0], by = bias[cb * 64 + c0 + 1];
#pragma unroll
        for (int rh = 0; rh < 2; rh++) {
            const int t = t0 + warpM + mt * 16 + rh * 8 + g;
            if (t < KLL) {
                const unsigned ux = f2t(acc[mt][nt][rh * 2 + 0] + bx);
                const unsigned uy = f2t(acc[mt][nt][rh * 2 + 1] + by);
                if (cb < HH) {
                    *(uint2*)(g_k + (((size_t)n) * KLL + t) * DH + c0) = make_uint2(ux, uy);
                } else {
                    g_vT[((size_t)n * DH + c0) * KLL + t] = ux;
                    g_vT[((size_t)n * DH + c0 + 1) * KLL + t] = uy;
                }
            }
        }
    }
}

// ---------------------------------------------------------------------------
// Flash attention: BLOCK_Q=128, BLOCK_K=64, 8 warps x 16 q-rows each.
// Warp-local online softmax (m/l in regs), diagonal tile skip.
// ---------------------------------------------------------------------------
#define FQ 0
#define FK (64 * UPW)
#define FV (96 * UPW)
#define FP (128 * UPW)
#define FTOT (192 * UPW)   // words = 25344 -> 101376 B

__global__ void __launch_bounds__(256) flash_kernel(const void* __restrict__ lengths)
{
    extern __shared__ unsigned smu[];
    unsigned* Qf = smu + FQ;
    unsigned* Kf = smu + FK;
    unsigned* Vf = smu + FV;
    unsigned* Pf = smu + FP;

    const int qt = gridDim.x - 1 - blockIdx.x;   // heavy first
    const int n = blockIdx.y, b = n >> 3;
    const int q0 = qt * 128;
    const int tid = threadIdx.x;
    const int lid = tid & 31, wid = tid >> 5;
    const int g = lid >> 2, tg = lid & 3;
    const int warpM = wid * 16;
    const int ldr = tid >> 4;          // 0..15
    const int ldc = (tid & 15) * 4;    // 0..60

    int ml = read_len(lengths, 0);
#pragma unroll
    for (int i = 1; i < BB; i++) { int v = read_len(lengths, i); if (v > ml) ml = v; }
    const int klen = read_len(lengths, b) + MMEM + (TQL - ml - SSUM);

    // Q -> A-frag smem (128x64), raw tf32 bits
#pragma unroll
    for (int i = 0; i < 8; i++) {
        const int r = i * 16 + ldr;
        const int q = q0 + r;
        uint4 v = (q < TQL) ? *(const uint4*)(g_q + ((size_t)n * TQL + q) * DH + ldc)
                            : make_uint4(0, 0, 0, 0);
        sts_afrag(Qf, 8, r, ldc, v);
    }

    float o[8][4];
#pragma unroll
    for (int nt = 0; nt < 8; nt++)
#pragma unroll
        for (int i = 0; i < 4; i++) o[nt][i] = 0.f;
    float m0 = NEG_INF, m1 = NEG_INF, l0 = 0.f, l1 = 0.f;

    const int qlo = q0 + warpM + g;
    const int nkt = min(17, 2 * qt + 3);
    for (int kt = 0; kt < nkt; kt++) {
        const int k0 = kt * 64;
        __syncthreads();
        // K (kseq x d) and V (d x kseq, from g_vT) -> B-frag, raw
#pragma unroll
        for (int i = 0; i < 4; i++) {
            const int r = i * 16 + ldr;
            uint4 kv = *(const uint4*)(g_k + ((size_t)n * KLL + k0 + r) * DH + ldc);
            sts_bfrag(Kf, 8, r, ldc, kv);
            uint4 vv = *(const uint4*)(g_vT + ((size_t)n * DH + r) * KLL + k0 + ldc);
            sts_bfrag(Vf, 8, r, ldc, vv);
        }
        __syncthreads();

        if (k0 > q0 + warpM + 15 + MMEM) continue;   // warp tile fully masked

        // S = Q K^T  (warp rows warpM..warpM+15)
        float s[8][4];
#pragma unroll
        for (int nt = 0; nt < 8; nt++)
#pragma unroll
            for (int i = 0; i < 4; i++) s[nt][i] = 0.f;
        {
            const uint4* Q4 = (const uint4*)Qf;
            const uint4* K4 = (const uint4*)Kf;
#pragma unroll
            for (int k8 = 0; k8 < 8; k8++) {
                uint4 a = Q4[(wid * 8 + k8) * UP4 + lid];
#pragma unroll
                for (int n16 = 0; n16 < 4; n16++) {
                    uint4 bq = K4[(n16 * 8 + k8) * UP4 + lid];
                    mma_t(s[n16 * 2], a, bq.x, bq.y);
                    mma_t(s[n16 * 2 + 1], a, bq.z, bq.w);
                }
            }
        }

        // mask (only near diagonal / pad boundary)
        if (k0 + 63 > q0 + warpM + MMEM || k0 + 64 > klen) {
#pragma unroll
            for (int nt = 0; nt < 8; nt++) {
                const int kb = k0 + nt * 8 + 2 * tg;
                s[nt][0] = (kb     <= qlo + MMEM && kb     < klen) ? s[nt][0] : NEG_INF;
                s[nt][1] = (kb + 1 <= qlo + MMEM && kb + 1 < klen) ? s[nt][1] : NEG_INF;
                s[nt][2] = (kb     <= qlo + 8 + MMEM && kb     < klen) ? s[nt][2] : NEG_INF;
                s[nt][3] = (kb + 1 <= qlo + 8 + MMEM && kb + 1 < klen) ? s[nt][3] : NEG_INF;
            }
        }

        // warp-local online softmax
        float mx0 = NEG_INF, mx1 = NEG_INF;
#pragma unroll
        for (int nt = 0; nt < 8; nt++) {
            mx0 = fmaxf(mx0, fmaxf(s[nt][0], s[nt][1]));
            mx1 = fmaxf(mx1, fmaxf(s[nt][2], s[nt][3]));
        }
        mx0 = fmaxf(mx0, __shfl_xor_sync(0xffffffffu, mx0, 1));
        mx0 = fmaxf(mx0, __shfl_xor_sync(0xffffffffu, mx0, 2));
        mx1 = fmaxf(mx1, __shfl_xor_sync(0xffffffffu, mx1, 1));
        mx1 = fmaxf(mx1, __shfl_xor_sync(0xffffffffu, mx1, 2));
        const float mn0 = fmaxf(m0, mx0), mn1 = fmaxf(m1, mx1);
        const float c0 = fexp(m0 - mn0), c1 = fexp(m1 - mn1);
        m0 = mn0; m1 = mn1;

        float sum0 = 0.f, sum1 = 0.f;
#pragma unroll
        for (int nt = 0; nt < 8; nt++) {
            const float p0 = fexp(s[nt][0] - m0);
            const float p1 = fexp(s[nt][1] - m0);
            const float p2 = fexp(s[nt][2] - m1);
            const float p3 = fexp(s[nt][3] - m1);
            sum0 += p0 + p1; sum1 += p2 + p3;
            const unsigned base = (unsigned)((wid * 8 + nt) * UPW);
            const int ln0 = g * 4 + ((2 * tg) & 3);
            const int ln1 = g * 4 + ((2 * tg + 1) & 3);
            const int sl = 2 * (tg >> 1);
            Pf[base + ln0 * 4 + sl + 0] = f2t(p0);
            Pf[base + ln1 * 4 + sl + 0] = f2t(p1);
            Pf[base + ln0 * 4 + sl + 1] = f2t(p2);
            Pf[base + ln1 * 4 + sl + 1] = f2t(p3);
            o[nt][0] *= c0; o[nt][1] *= c0;
            o[nt][2] *= c1; o[nt][3] *= c1;
        }
        sum0 += __shfl_xor_sync(0xffffffffu, sum0, 1);
        sum0 += __shfl_xor_sync(0xffffffffu, sum0, 2);
        sum1 += __shfl_xor_sync(0xffffffffu, sum1, 1);
        sum1 += __shfl_xor_sync(0xffffffffu, sum1, 2);
        l0 = l0 * c0 + sum0;
        l1 = l1 * c1 + sum1;

        __syncwarp();
        // O += P V  (all warp-local A, shared B)
        {
            const uint4* P4 = (const uint4*)Pf;
            const uint4* V4 = (const uint4*)Vf;
#pragma unroll
            for (int k8 = 0; k8 < 8; k8++) {
                uint4 a = P4[(wid * 8 + k8) * UP4 + lid];
#pragma unroll
                for (int n16 = 0; n16 < 4; n16++) {
                    uint4 bv = V4[(n16 * 8 + k8) * UP4 + lid];
                    mma_t(o[n16 * 2], a, bv.x, bv.y);
                    mma_t(o[n16 * 2 + 1], a, bv.z, bv.w);
                }
            }
        }
    }

    const float i0 = 1.f / l0, i1 = 1.f / l1;
    const int qhi = qlo + 8;
#pragma unroll
    for (int nt = 0; nt < 8; nt++) {
        const int c = nt * 8 + 2 * tg;
        if (qlo < TQL) {
            uint2 v; v.x = f2t(o[nt][0] * i0); v.y = f2t(o[nt][1] * i0);
            *(uint2*)(g_attn + ((size_t)n * TQL + qlo) * DH + c) = v;
        }
        if (qhi < TQL) {
            uint2 v; v.x = f2t(o[nt][2] * i1); v.y = f2t(o[nt][3] * i1);
            *(uint2*)(g_attn + ((size_t)n * TQL + qhi) * DH + c) = v;
        }
    }
}

// ---------------------------------------------------------------------------
__global__ void __launch_bounds__(256) out_proj_kernel(
    const float* __restrict__ bias, float* __restrict__ out)
{
    __shared__ ProjSmem s;
    const int t0 = blockIdx.x * 128;
    const int cby = blockIdx.y, b = blockIdx.z;
    PROJ_PROLOG;

    int tr[4]; bool tv[4];
#pragma unroll
    for (int i = 0; i < 4; i++) { tr[i] = t0 + i * 32 + lr; tv[i] = tr[i] < TQL; }
    const unsigned* bp0 = g_wo + (size_t)(cby * 64 + lr) * DDIM;
    const unsigned* bp1 = g_wo + (size_t)(cby * 64 + 32 + lr) * DDIM;

    auto lda = [&](int k0, uint4* pa) {
        const int hh = k0 >> 6, ko = (k0 & 63) + lc;
#pragma unroll
        for (int i = 0; i < 4; i++)
            pa[i] = tv[i] ? *(const uint4*)(g_attn +
                     ((size_t)(b * HH + hh) * TQL + tr[i]) * DH + ko)
                          : make_uint4(0, 0, 0, 0);
    };

    uint4 pa[4], pb[2];
    lda(0, pa);
    pb[0] = *(const uint4*)(bp0 + lc); pb[1] = *(const uint4*)(bp1 + lc);

    for (int k0 = 0; k0 < DDIM; k0 += 32) {
        __syncthreads();
#pragma unroll
        for (int i = 0; i < 4; i++) sts_afrag(s.Af, 4, i * 32 + lr, lc, pa[i]);
        sts_bfrag(s.Bf, 4, lr, lc, pb[0]);
        sts_bfrag(s.Bf, 4, 32 + lr, lc, pb[1]);
        __syncthreads();
        if (k0 + 32 < DDIM) {
            lda(k0 + 32, pa);
            const int kn = k0 + 32 + lc;
            pb[0] = *(const uint4*)(bp0 + kn); pb[1] = *(const uint4*)(bp1 + kn);
        }
        proj_mma(s, lid, wid, acc);
    }

    const size_t mems_base = (size_t)(TQL - SSUM) * BB * DDIM;
#pragma unroll
    for (int mt = 0; mt < 2; mt++)
#pragma unroll
    for (int nt = 0; nt < 4; nt++) {
        const int c0 = cby * 64 + warpN + nt * 8 + 2 * tg;
        const float bx = bias[c0], by = bias[c0 + 1];
#pragma unroll
        for (int rh = 0; rh < 2; rh++) {
            const int tt = t0 + warpM + mt * 16 + rh * 8 + g;
            if (tt >= TQL - 1) continue;   // drop t=1071 and padding
            float2 v;
            v.x = acc[mt][nt][rh * 2 + 0] + bx;
            v.y = acc[mt][nt][rh * 2 + 1] + by;
            if (tt < TQL - SSUM) {
                *(float2*)(out + ((size_t)tt * BB + b) * DDIM + c0) = v;
            } else {
                v.x = fminf(fmaxf(v.x, -10.f), 10.f);
                v.y = fminf(fmaxf(v.y, -10.f), 10.f);
                *(float2*)(out + mems_base +
                           ((size_t)(tt - (TQL - SSUM)) * BB + b) * DDIM + c0) = v;
            }
        }
    }
}

// ---------------------------------------------------------------------------
extern "C" void kernel_launch(void* const* d_in, const int* in_sizes, int n_in,
                              void* d_out, int out_size)
{
    const float* utt  = (const float*)d_in[0];
    const void*  len  = (const void*)d_in[1];
    const float* rc   = (const float*)d_in[2];
    const float* summ = (const float*)d_in[3];
    const float* mems = (const float*)d_in[4];
    // d_in[5] = attention_mask (deterministic; computed analytically in-kernel)
    const float* Wq   = (const float*)d_in[6];
    const float* bq   = (const float*)d_in[7];
    const float* Wkv  = (const float*)d_in[8];
    const float* bkv  = (const float*)d_in[9];
    const float* Wo   = (const float*)d_in[10];
    const float* bo   = (const float*)d_in[11];
    float* out = (float*)d_out;

    // device-global scratch addresses (host side)
    unsigned *p_in, *p_wq, *p_wkv, *p_wo;
    cudaGetSymbolAddress((void**)&p_in, g_in);
    cudaGetSymbolAddress((void**)&p_wq, g_wq);
    cudaGetSymbolAddress((void**)&p_wkv, g_wkv);
    cudaGetSymbolAddress((void**)&p_wo, g_wo);

    auto cvt = [&](const float* src, unsigned* dst, int nfloats) {
        const int n4 = nfloats / 4;
        cvt_kernel<<<(n4 + 255) / 256, 256>>>((const float4*)src, (uint4*)dst, n4);
    };
    // packed input: rows [mems 0..15 | rc 16..47 | utt 48..1071 | summ 1072..1087]
    cvt(mems, p_in,                         MMEM * BB * DDIM);
    cvt(rc,   p_in + 16 * BB * DDIM,        RR * BB * DDIM);
    cvt(utt,  p_in + 48 * BB * DDIM,        TT * BB * DDIM);
    cvt(summ, p_in + 1072 * BB * DDIM,      SSUM * BB * DDIM);
    cvt(Wq,   p_wq,  512 * 512);
    cvt(Wkv,  p_wkv, 1024 * 512);
    cvt(Wo,   p_wo,  512 * 512);

    const int flash_smem = FTOT * (int)sizeof(unsigned);   // 101376 B
    cudaFuncSetAttribute(flash_kernel,
                         cudaFuncAttributeMaxDynamicSharedMemorySize, flash_smem);

    proj_q_kernel  <<<dim3(9, 8, BB), 256>>>(bq);
    proj_kv_kernel <<<dim3(9, 16, BB), 256>>>(bkv);
    flash_kernel   <<<dim3(9, NH), 256, flash_smem>>>(len);
    out_proj_kernel<<<dim3(9, 8, BB), 256>>>(bo, out);
}